// round 16
// baseline (speedup 1.0000x reference)
#include <cuda_runtime.h>
#include <cuda_fp16.h>
#include <math.h>
#include <stdint.h>

// ---------------- problem constants (GPT-2 small forward) ----------------
#define Bq   8
#define Tt   1024
#define NT   8192          // B*T tokens
#define Cd   768
#define Hh   12
#define HSd  64
#define Fd   3072
#define Ll   12
#define Vv   50257
#define VPAD 50304         // multiple of 128
#define QKVS 2304          // fused qkv width
#define GEMM_GRID 304      // ~2 CTAs/SM on 152 SMs

// ---------------- scratch (device globals: allocation-free) --------------
__device__ float  g_x[(size_t)NT * Cd];        // residual stream (fp32)
__device__ __half g_h[(size_t)NT * Cd];        // LN output (fp16)
__device__ __half g_qkv[(size_t)NT * QKVS];    // fused q|k|v (fp16)
__device__ __half g_ob[(size_t)NT * Cd];       // attention out (fp16)
__device__ __half g_f[(size_t)NT * Fd];        // MLP hidden (fp16)
__device__ float  g_rowloss[NT];
__device__ float  g_lm[NT];
__device__ float  g_ls[NT];
__device__ float  g_lt[NT];

// fp16 weights, pre-transposed to [N][K] (K-contiguous)
#define OFF_QKV ((size_t)0)                        // [L][2304][768]
#define OFF_WO  ((size_t)21233664)                 // [L][768][768]
#define OFF_W1  ((size_t)28311552)                 // [L][3072][768]
#define OFF_W2  ((size_t)56623104)                 // [L][768][3072]
#define OFF_HD  ((size_t)84934656)                 // [VPAD][768]
#define WTH_TOTAL ((size_t)84934656 + (size_t)VPAD * Cd)
__device__ __half g_wth[WTH_TOTAL];

// ---------------- helpers ----------------
__device__ __forceinline__ uint32_t smem_u32(const void* p) {
    uint32_t a;
    asm("{ .reg .u64 t; cvta.to.shared.u64 t, %1; cvt.u32.u64 %0, t; }" : "=r"(a) : "l"(p));
    return a;
}

__device__ __forceinline__ void cp16(uint32_t saddr, const void* gaddr) {
    asm volatile("cp.async.cg.shared.global [%0], [%1], 16;" :: "r"(saddr), "l"(gaddr));
}
#define CP_COMMIT() asm volatile("cp.async.commit_group;" ::: "memory")
#define CP_WAIT1()  asm volatile("cp.async.wait_group 1;" ::: "memory")
#define CP_WAIT0()  asm volatile("cp.async.wait_group 0;" ::: "memory")

__device__ __forceinline__ void mma16(float* c, const uint32_t* a, const uint32_t* b) {
    asm volatile(
        "mma.sync.aligned.m16n8k16.row.col.f32.f16.f16.f32 "
        "{%0,%1,%2,%3}, {%4,%5,%6,%7}, {%8,%9}, {%0,%1,%2,%3};\n"
        : "+f"(c[0]), "+f"(c[1]), "+f"(c[2]), "+f"(c[3])
        : "r"(a[0]), "r"(a[1]), "r"(a[2]), "r"(a[3]), "r"(b[0]), "r"(b[1]));
}

__device__ __forceinline__ void ldsm_x4(uint32_t* r, uint32_t saddr) {
    asm volatile("ldmatrix.sync.aligned.m8n8.x4.shared.b16 {%0,%1,%2,%3}, [%4];"
                 : "=r"(r[0]), "=r"(r[1]), "=r"(r[2]), "=r"(r[3]) : "r"(saddr));
}
__device__ __forceinline__ void ldsm_x2_trans(uint32_t* r, uint32_t saddr) {
    asm volatile("ldmatrix.sync.aligned.m8n8.x2.trans.shared.b16 {%0,%1}, [%2];"
                 : "=r"(r[0]), "=r"(r[1]) : "r"(saddr));
}

// ---------------- block reduce helpers ----------------
__device__ __forceinline__ float blockReduceSum256(float v) {
    __shared__ float sh[8];
    int lane = threadIdx.x & 31, w = threadIdx.x >> 5;
#pragma unroll
    for (int o = 16; o; o >>= 1) v += __shfl_xor_sync(0xffffffffu, v, o);
    if (lane == 0) sh[w] = v;
    __syncthreads();
    float r = (threadIdx.x < 8) ? sh[threadIdx.x] : 0.f;
    if (w == 0) {
#pragma unroll
        for (int o = 4; o; o >>= 1) r += __shfl_xor_sync(0xffffffffu, r, o);
    }
    __syncthreads();
    if (threadIdx.x == 0) sh[0] = r;
    __syncthreads();
    return sh[0];
}

__device__ __forceinline__ float blockReduceMax256(float v) {
    __shared__ float sh[8];
    int lane = threadIdx.x & 31, w = threadIdx.x >> 5;
#pragma unroll
    for (int o = 16; o; o >>= 1) v = fmaxf(v, __shfl_xor_sync(0xffffffffu, v, o));
    if (lane == 0) sh[w] = v;
    __syncthreads();
    float r = (threadIdx.x < 8) ? sh[threadIdx.x] : -1e30f;
    if (w == 0) {
#pragma unroll
        for (int o = 4; o; o >>= 1) r = fmaxf(r, __shfl_xor_sync(0xffffffffu, r, o));
    }
    __syncthreads();
    if (threadIdx.x == 0) sh[0] = r;
    __syncthreads();
    return sh[0];
}

// ---------------- weight prep: transpose f32 [K][N] -> fp16 [Npad][K] -----
__global__ __launch_bounds__(256) void transpose_h_kernel(
    const float* __restrict__ src, __half* __restrict__ dst,
    int K, int N, int Npad, size_t sstride, size_t dstride) {
    src += (size_t)blockIdx.z * sstride;
    dst += (size_t)blockIdx.z * dstride;
    __shared__ float t[64][33];
    const int kb = blockIdx.y * 64, nb = blockIdx.x * 32;
    const int warp = threadIdx.x >> 5, lane = threadIdx.x & 31;
#pragma unroll
    for (int j = 0; j < 8; j++) {
        int r = warp * 8 + j;
        int k = kb + r, n = nb + lane;
        t[r][lane] = (k < K && n < N) ? src[(size_t)k * N + n] : 0.f;
    }
    __syncthreads();
#pragma unroll
    for (int j = 0; j < 4; j++) {
        int nl = warp * 4 + j;
        int n = nb + nl;
        int k = kb + lane * 2;
        if (n < Npad && k < K) {
            __half2 v = __floats2half2_rn(t[lane * 2][nl], t[lane * 2 + 1][nl]);
            *(__half2*)(dst + (size_t)n * K + k) = v;
        }
    }
}

// =====================================================================
// fp16 mma.sync GEMM (persistent): C[M,Nn] = A[M,K](fp16) @ Wt[N][K]^T
// BM=128, BN=128, BK=64, 256 threads; cp.async 3-stage; ldmatrix x4 loads.
// Prefetch finely interleaved: 2 cp.async after each ks (A:0,1  B:2,3).
// LSE: accumulate per-row sum(exp(logit)) into lse[] via atomics.
// =====================================================================
#define ASTH 72
#define HTILE_H (128 * ASTH)            // 9216 halfs
#define HSTG_H  (2 * HTILE_H)           // A + B
#define NSTG 3
#define GEMM_SMEM (NSTG * HSTG_H * 2)   // 110592 bytes

template<bool BIAS, bool RELU, bool RES, bool NBOUND, bool OUTH, bool LSE>
__global__ __launch_bounds__(256, 2) void mma_gemm(
    const __half* __restrict__ A, const __half* __restrict__ Wt,
    const float* __restrict__ bias, const float* __restrict__ res,
    void* __restrict__ Cv, int M, int Nn, int K, int ntn,
    float* __restrict__ lse) {
    extern __shared__ __half smh[];
    const uint32_t su = smem_u32(smh);
    const int tid = threadIdx.x;
    const int warp = tid >> 5, lane = tid & 31;
    const int g = lane >> 2, t4 = lane & 3;
    const int wm = warp >> 2, wn = warp & 3;
    const int warp_m0 = wm * 64, warp_n0 = wn * 32;

    const int mA = lane >> 3;
    const int aRow = (mA & 1) * 8 + (lane & 7);
    const int aCol = (mA >> 1) * 8;
    uint32_t offA[4];
#pragma unroll
    for (int mt = 0; mt < 4; mt++)
        offA[mt] = (uint32_t)((warp_m0 + mt * 16 + aRow) * ASTH + aCol);
    const int tIdx = lane >> 3;
    const int bRowAdd = (tIdx >> 1) * 8 + (lane & 7);
    const int bColAdd = (tIdx & 1) * 8;
    uint32_t offB2[2];
#pragma unroll
    for (int nt2 = 0; nt2 < 2; nt2++)
        offB2[nt2] = (uint32_t)(HTILE_H + (warp_n0 + nt2 * 16 + bRowAdd) * ASTH + bColAdd);

    const int nk = K >> 6;
    const int ntm = M >> 7;
    const int ntiles = ntm * ntn;

    for (int tile = blockIdx.x; tile < ntiles; tile += gridDim.x) {
        const int m0 = (tile % ntm) * 128;
        const int n0 = (tile / ntm) * 128;
        __syncthreads();   // guard smem reuse across tiles

        float acc[4][4][4];
#pragma unroll
        for (int mt = 0; mt < 4; mt++)
#pragma unroll
            for (int nt = 0; nt < 4; nt++)
#pragma unroll
                for (int j = 0; j < 4; j++) acc[mt][nt][j] = 0.f;

        // half-loads: 2 cp.async per thread (chunks [h*2, h*2+1])
        auto load_A_half = [&](int s, int kb, int hh) {
            uint32_t sa = su + (uint32_t)s * HSTG_H * 2;
#pragma unroll
            for (int i = hh * 2; i < hh * 2 + 2; i++) {
                int ch = tid + i * 256;
                int r = ch >> 3, c = ch & 7;
                cp16(sa + (uint32_t)(r * ASTH + c * 8) * 2,
                     A + (size_t)(m0 + r) * K + kb + c * 8);
            }
        };
        auto load_B_half = [&](int s, int kb, int hh) {
            uint32_t sb = su + (uint32_t)s * HSTG_H * 2 + HTILE_H * 2;
#pragma unroll
            for (int i = hh * 2; i < hh * 2 + 2; i++) {
                int ch = tid + i * 256;
                int r = ch >> 3, c = ch & 7;
                cp16(sb + (uint32_t)(r * ASTH + c * 8) * 2,
                     Wt + (size_t)(n0 + r) * K + kb + c * 8);
            }
        };

        load_A_half(0, 0, 0);  load_A_half(0, 0, 1);
        load_B_half(0, 0, 0);  load_B_half(0, 0, 1);  CP_COMMIT();
        load_A_half(1, 64, 0); load_A_half(1, 64, 1);
        load_B_half(1, 64, 0); load_B_half(1, 64, 1); CP_COMMIT();

        int s = 0;
        for (int kc = 0; kc < nk; kc++) {
            if (kc + 1 < nk) CP_WAIT1(); else CP_WAIT0();
            __syncthreads();

            const bool pf = (kc + 2 < nk);
            int sw = s + 2; if (sw >= NSTG) sw -= NSTG;
            const int kb2 = (kc + 2) * 64;

            const uint32_t sbase = su + (uint32_t)s * HSTG_H * 2;
#pragma unroll
            for (int ks = 0; ks < 4; ks++) {
                const int kk = ks * 16;
                uint32_t af[4][4], bf[4][2];
#pragma unroll
                for (int mt = 0; mt < 4; mt++)
                    ldsm_x4(af[mt], sbase + (offA[mt] + kk) * 2);
#pragma unroll
                for (int nt2 = 0; nt2 < 2; nt2++) {
                    uint32_t bt[4];
                    ldsm_x4(bt, sbase + (offB2[nt2] + kk) * 2);
                    bf[nt2 * 2 + 0][0] = bt[0]; bf[nt2 * 2 + 0][1] = bt[1];
                    bf[nt2 * 2 + 1][0] = bt[2]; bf[nt2 * 2 + 1][1] = bt[3];
                }
#pragma unroll
                for (int mt = 0; mt < 4; mt++)
#pragma unroll
                    for (int nt = 0; nt < 4; nt++)
                        mma16(acc[mt][nt], af[mt], bf[nt]);

                // finely interleaved prefetch: 2 cp.async per ks group, issued
                // after that group's ldmatrix+MMAs (LSU bursts stay small).
                if (pf) {
                    if (ks == 0) load_A_half(sw, kb2, 0);
                    else if (ks == 1) load_A_half(sw, kb2, 1);
                    else if (ks == 2) load_B_half(sw, kb2, 0);
                    else { load_B_half(sw, kb2, 1); CP_COMMIT(); }
                }
            }

            if (++s == NSTG) s = 0;
        }

        // ---- epilogue ----
        float rowsum[4][2];
        if (LSE) {
#pragma unroll
            for (int mt = 0; mt < 4; mt++) { rowsum[mt][0] = 0.f; rowsum[mt][1] = 0.f; }
        }
#pragma unroll
        for (int mt = 0; mt < 4; mt++) {
            int r0 = m0 + warp_m0 + mt * 16 + g;
#pragma unroll
            for (int nt = 0; nt < 4; nt++) {
                int cn = n0 + warp_n0 + nt * 8 + t4 * 2;
                float* a4 = acc[mt][nt];
                float b0 = 0.f, b1 = 0.f;
                if (BIAS) {
                    if (!NBOUND) { b0 = bias[cn]; b1 = bias[cn + 1]; }
                    else {
                        b0 = (cn < Nn) ? bias[cn] : 0.f;
                        b1 = (cn + 1 < Nn) ? bias[cn + 1] : 0.f;
                    }
                }
#pragma unroll
                for (int half_ = 0; half_ < 2; half_++) {
                    int r = r0 + half_ * 8;
                    float v0 = a4[half_ * 2 + 0] + b0;
                    float v1 = a4[half_ * 2 + 1] + b1;
                    if (RELU) { v0 = fmaxf(v0, 0.f); v1 = fmaxf(v1, 0.f); }
                    size_t off = (size_t)r * Nn + cn;
                    if (!NBOUND) {
                        if (RES) { v0 += res[off]; v1 += res[off + 1]; }
                        if (OUTH) {
                            *(__half2*)((__half*)Cv + off) = __floats2half2_rn(v0, v1);
                        } else {
                            *(float2*)((float*)Cv + off) = make_float2(v0, v1);
                        }
                    } else {
                        float* C = (float*)Cv;
                        if (cn < Nn) {
                            if (RES) v0 += res[off];
                            C[off] = v0;
                            if (LSE) rowsum[mt][half_] += __expf(v0);
                        }
                        if (cn + 1 < Nn) {
                            if (RES) v1 += res[off + 1];
                            C[off + 1] = v1;
                            if (LSE) rowsum[mt][half_] += __expf(v1);
                        }
                    }
                }
            }
        }
        if (LSE) {
#pragma unroll
            for (int mt = 0; mt < 4; mt++) {
#pragma unroll
                for (int half_ = 0; half_ < 2; half_++) {
                    float sc = rowsum[mt][half_];
                    sc += __shfl_xor_sync(0xffffffffu, sc, 1);
                    sc += __shfl_xor_sync(0xffffffffu, sc, 2);
                    if (t4 == 0) {
                        int r = m0 + warp_m0 + mt * 16 + g + half_ * 8;
                        atomicAdd(&lse[r], sc);
                    }
                }
            }
        }
    }
}

// ---------------- embedding (float4 vectorized) ----------------
__global__ void embed_kernel(const int* __restrict__ inp,
                             const float* __restrict__ tok,
                             const float* __restrict__ pos,
                             float* __restrict__ x) {
    int i = blockIdx.x;
    int t = i & (Tt - 1);
    int v = inp[i];
    const float4* te = (const float4*)(tok + (size_t)v * Cd);
    const float4* pe = (const float4*)(pos + (size_t)t * Cd);
    float4* xo = (float4*)(x + (size_t)i * Cd);
    for (int c = threadIdx.x; c < Cd / 4; c += blockDim.x) {
        float4 a = te[c], b = pe[c];
        a.x += b.x; a.y += b.y; a.z += b.z; a.w += b.w;
        xo[c] = a;
    }
}

// ---------------- layernorm: warp per row, fp16 output ----------------
__global__ __launch_bounds__(256) void ln_kernel(const float* __restrict__ x,
                                                 const float* __restrict__ g,
                                                 const float* __restrict__ b,
                                                 __half* __restrict__ out) {
    const int warp = threadIdx.x >> 5, lane = threadIdx.x & 31;
    const int row = blockIdx.x * 8 + warp;
    const float4* xr = (const float4*)(x + (size_t)row * Cd);
    const float4* gp = (const float4*)g;
    const float4* bp = (const float4*)b;
    __half* orow = out + (size_t)row * Cd;

    float4 v[6];
    float s = 0.f;
#pragma unroll
    for (int i = 0; i < 6; i++) {
        v[i] = xr[lane + i * 32];
        s += v[i].x + v[i].y + v[i].z + v[i].w;
    }
#pragma unroll
    for (int o = 16; o; o >>= 1) s += __shfl_xor_sync(0xffffffffu, s, o);
    float mean = s * (1.0f / Cd);

    float vs = 0.f;
#pragma unroll
    for (int i = 0; i < 6; i++) {
        float dx = v[i].x - mean, dy = v[i].y - mean,
              dz = v[i].z - mean, dw = v[i].w - mean;
        vs += dx * dx + dy * dy + dz * dz + dw * dw;
    }
#pragma unroll
    for (int o = 16; o; o >>= 1) vs += __shfl_xor_sync(0xffffffffu, vs, o);
    float rstd = rsqrtf(vs * (1.0f / Cd) + 1e-5f);

#pragma unroll
    for (int i = 0; i < 6; i++) {
        float4 gg = gp[lane + i * 32];
        float4 bb = bp[lane + i * 32];
        __half2 h01 = __floats2half2_rn((v[i].x - mean) * rstd * gg.x + bb.x,
                                        (v[i].y - mean) * rstd * gg.y + bb.y);
        __half2 h23 = __floats2half2_rn((v[i].z - mean) * rstd * gg.z + bb.z,
                                        (v[i].w - mean) * rstd * gg.w + bb.w);
        uint2 pk = make_uint2(*(uint32_t*)&h01, *(uint32_t*)&h23);
        *(uint2*)(orow + (lane + i * 32) * 4) = pk;
    }
}

// ---------------- fp16 -> fp32 convert (fallback path) ----------------
__global__ void h2f_kernel(const __half* __restrict__ src, float* __restrict__ dst, size_t n) {
    for (size_t i = (size_t)blockIdx.x * blockDim.x + threadIdx.x; i < n;
         i += (size_t)gridDim.x * blockDim.x)
        dst[i] = __half2float(src[i]);
}

// ---------------- SIMT SGEMM (loss-only fallback path) ----------------
template<bool BIAS, bool RELU, bool RES>
__global__ __launch_bounds__(256) void sgemm_kernel(
    const float* __restrict__ A, const float* __restrict__ W,
    const float* __restrict__ bias, const float* __restrict__ res,
    float* __restrict__ Cout, int M, int Nn, int K, int ldw) {
    __shared__ float As[16][132];
    __shared__ float Bs[16][64];
    int tid = threadIdx.x;
    int m0 = blockIdx.x * 128;
    int n0 = blockIdx.y * 64;
    int tx = tid & 15, ty = tid >> 4;
    float acc[8][4];
#pragma unroll
    for (int i = 0; i < 8; i++)
#pragma unroll
        for (int j = 0; j < 4; j++) acc[i][j] = 0.f;
    int am = tid >> 1;
    int ak = (tid & 1) * 8;
    int bk = tid >> 4;
    int bn = (tid & 15) * 4;
    for (int k0 = 0; k0 < K; k0 += 16) {
        const float* Ap = A + (size_t)(m0 + am) * K + k0 + ak;
        float4 a0 = *(const float4*)Ap;
        float4 a1 = *(const float4*)(Ap + 4);
        As[ak + 0][am] = a0.x; As[ak + 1][am] = a0.y;
        As[ak + 2][am] = a0.z; As[ak + 3][am] = a0.w;
        As[ak + 4][am] = a1.x; As[ak + 5][am] = a1.y;
        As[ak + 6][am] = a1.z; As[ak + 7][am] = a1.w;
        int gn = n0 + bn;
        const float* Wp = W + (size_t)(k0 + bk) * ldw + gn;
        float4 bv;
        bv.x = (gn + 0 < Nn) ? Wp[0] : 0.f;
        bv.y = (gn + 1 < Nn) ? Wp[1] : 0.f;
        bv.z = (gn + 2 < Nn) ? Wp[2] : 0.f;
        bv.w = (gn + 3 < Nn) ? Wp[3] : 0.f;
        *(float4*)&Bs[bk][bn] = bv;
        __syncthreads();
#pragma unroll
        for (int kk = 0; kk < 16; kk++) {
            float4 a04 = *(const float4*)&As[kk][ty * 8];
            float4 a14 = *(const float4*)&As[kk][ty * 8 + 4];
            float4 b4  = *(const float4*)&Bs[kk][tx * 4];
            float a[8] = {a04.x, a04.y, a04.z, a04.w, a14.x, a14.y, a14.z, a14.w};
            float bb[4] = {b4.x, b4.y, b4.z, b4.w};
#pragma unroll
            for (int i = 0; i < 8; i++)
#pragma unroll
                for (int j = 0; j < 4; j++)
                    acc[i][j] += a[i] * bb[j];
        }
        __syncthreads();
    }
    int nbase = n0 + tx * 4;
#pragma unroll
    for (int i = 0; i < 8; i++) {
        size_t rowoff = (size_t)(m0 + ty * 8 + i) * Nn;
#pragma unroll
        for (int j = 0; j < 4; j++) {
            int n = nbase + j;
            if (n < Nn) {
                float v = acc[i][j];
                if (BIAS) v += bias[n];
                if (RELU) v = fmaxf(v, 0.f);
                if (RES) v += res[rowoff + n];
                Cout[rowoff + n] = v;
            }
        }
    }
}

// =====================================================================
// fp16 tensor-core flash attention (S exact; P split hi/lo fp16)
// cp.async double-buffered K/V tiles (row-major [j][d]); V via ldmatrix.trans
// =====================================================================
#define AST2 72
#define ATILE (64 * AST2)
#define ATTN_SMEM (6 * ATILE * 2)   // 55296 bytes

__global__ __launch_bounds__(128, 4) void attn_tc_kernel(const __half* __restrict__ QKV,
                                                         __half* __restrict__ O) {
    extern __shared__ __half sme[];
    __half* Ks0 = sme;
    __half* Vs0 = Ks0 + ATILE;
    __half* Ks1 = Vs0 + ATILE;
    __half* Vs1 = Ks1 + ATILE;
    __half* Ph  = Vs1 + ATILE;
    __half* Pl  = Ph + ATILE;
    const uint32_t suK[2] = { smem_u32(Ks0), smem_u32(Ks1) };

    const int qt = gridDim.x - 1 - blockIdx.x;
    const int bh = blockIdx.y;
    const int b = bh / Hh, h = bh % Hh;
    const int tid = threadIdx.x;
    const int warp = tid >> 5, lane = tid & 31;
    const int g = lane >> 2, t4 = lane & 3;
    const int r0l = warp * 16 + g;
    const int r1l = r0l + 8;

    auto load_kv = [&](int stage, int kt) {
        uint32_t sk = suK[stage];
        const __half* base = QKV + (size_t)(b * Tt + kt * 64) * QKVS + h * HSd;
#pragma unroll
        for (int i = 0; i < 4; i++) {
            int ch = tid + i * 128;
            int r = ch >> 3, c8 = (ch & 7) * 8;
            const __half* grow = base + (size_t)r * QKVS + c8;
            cp16(sk + (uint32_t)(r * AST2 + c8) * 2, grow + Cd);
            cp16(sk + (uint32_t)(ATILE + r * AST2 + c8) * 2, grow + 2 * Cd);
        }
        CP_COMMIT();
    };

    load_kv(0, 0);
    if (qt >= 1) load_kv(1, 1);

#pragma unroll
    for (int i = 0; i < 4; i++) {
        int ch = tid + i * 128;
        int r = ch >> 3, c8 = (ch & 7) * 8;
        float4 v = *(const float4*)(QKV + (size_t)(b * Tt + qt * 64 + r) * QKVS + h * HSd + c8);
        *(float4*)(Ph + r * AST2 + c8) = v;
    }
    __syncthreads();

    uint32_t qf[4][4];
#pragma unroll
    for (int ks = 0; ks < 4; ks++) {
        int kk = ks * 16;
        qf[ks][0] = *(const uint32_t*)(Ph + r0l * AST2 + kk + 2 * t4);
        qf[ks][1] = *(const uint32_t*)(Ph + r1l * AST2 + kk + 2 * t4);
        qf[ks][2] = *(const uint32_t*)(Ph + r0l * AST2 + kk + 2 * t4 + 8);
        qf[ks][3] = *(const uint32_t*)(Ph + r1l * AST2 + kk + 2 * t4 + 8);
    }

    const int vRow = (lane & 7) + ((lane >> 3) & 1) * 8;

    float o[8][4];
#pragma unroll
    for (int nt = 0; nt < 8; nt++)
#pragma unroll
        for (int j = 0; j < 4; j++) o[nt][j] = 0.f;
    float m0 = -1e30f, m1 = -1e30f, l0 = 0.f, l1 = 0.f;

    for (int kt = 0; kt <= qt; kt++) {
        const int st = kt & 1;
        if (kt < qt) CP_WAIT1(); else CP_WAIT0();
        __syncthreads();

        const __half* Ks = (st == 0) ? Ks0 : Ks1;
        const uint32_t vbase = suK[st] + ATILE * 2;

        float sacc[8][4];
#pragma unroll
        for (int nt = 0; nt < 8; nt++)
#pragma unroll
            for (int j = 0; j < 4; j++) sacc[nt][j] = 0.f;
#pragma unroll
        for (int ks = 0; ks < 4; ks++) {
            int kk = ks * 16;
#pragma unroll
            for (int nt = 0; nt < 8; nt++) {
                int j = nt * 8 + g;
                uint32_t bf[2];
                bf[0] = *(const uint32_t*)(Ks + j * AST2 + kk + 2 * t4);
                bf[1] = *(const uint32_t*)(Ks + j * AST2 + kk + 2 * t4 + 8);
                mma16(sacc[nt], qf[ks], bf);
            }
        }
#pragma unroll
        for (int nt = 0; nt < 8; nt++)
#pragma unroll
            for (int j = 0; j < 4; j++) sacc[nt][j] *= 0.125f;

        if (kt == qt) {
#pragma unroll
            for (int nt = 0; nt < 8; nt++) {
                int c0 = nt * 8 + 2 * t4;
                if (c0     > r0l) sacc[nt][0] = -1e30f;
                if (c0 + 1 > r0l) sacc[nt][1] = -1e30f;
                if (c0     > r1l) sacc[nt][2] = -1e30f;
                if (c0 + 1 > r1l) sacc[nt][3] = -1e30f;
            }
        }

        float tm0 = -1e30f, tm1 = -1e30f;
#pragma unroll
        for (int nt = 0; nt < 8; nt++) {
            tm0 = fmaxf(tm0, fmaxf(sacc[nt][0], sacc[nt][1]));
            tm1 = fmaxf(tm1, fmaxf(sacc[nt][2], sacc[nt][3]));
        }
        tm0 = fmaxf(tm0, __shfl_xor_sync(0xffffffffu, tm0, 1));
        tm0 = fmaxf(tm0, __shfl_xor_sync(0xffffffffu, tm0, 2));
        tm1 = fmaxf(tm1, __shfl_xor_sync(0xffffffffu, tm1, 1));
        tm1 = fmaxf(tm1, __shfl_xor_sync(0xffffffffu, tm1, 2));
        float mN0 = fmaxf(m0, tm0), mN1 = fmaxf(m1, tm1);
        float a0 = __expf(m0 - mN0), a1 = __expf(m1 - mN1);
        m0 = mN0; m1 = mN1;

        float sum0 = 0.f, sum1 = 0.f;
#pragma unroll
        for (int nt = 0; nt < 8; nt++) {
            float p0 = __expf(sacc[nt][0] - mN0);
            float p1 = __expf(sacc[nt][1] - mN0);
            float p2 = __expf(sacc[nt][2] - mN1);
            float p3 = __expf(sacc[nt][3] - mN1);
            sum0 += p0 + p1;
            sum1 += p2 + p3;
            int c0 = nt * 8 + 2 * t4;
            __half2 h01 = __floats2half2_rn(p0, p1);
            __half2 h23 = __floats2half2_rn(p2, p3);
            *(__half2*)(Ph + r0l * AST2 + c0) = h01;
            *(__half2*)(Ph + r1l * AST2 + c0) = h23;
            *(__half2*)(Pl + r0l * AST2 + c0) =
                __floats2half2_rn(p0 - __half2float(__low2half(h01)),
                                  p1 - __half2float(__high2half(h01)));
            *(__half2*)(Pl + r1l * AST2 + c0) =
                __floats2half2_rn(p2 - __half2float(__low2half(h23)),
                                  p3 - __half2float(__high2half(h23)));
        }
        sum0 += __shfl_xor_sync(0xffffffffu, sum0, 1);
        sum0 += __shfl_xor_sync(0xffffffffu, sum0, 2);
        sum1 += __shfl_xor_sync(0xffffffffu, sum1, 1);
        sum1 += __shfl_xor_sync(0xffffffffu, sum1, 2);
        l0 = l0 * a0 + sum0;
        l1 = l1 * a1 + sum1;
#pragma unroll
        for (int nt = 0; nt < 8; nt++) {
            o[nt][0] *= a0; o[nt][1] *= a0;
            o[nt][2] *= a1; o[nt][3] *= a1;
        }
        __syncwarp();

#pragma unroll
        for (int ks = 0; ks < 4; ks++) {
            int kk = ks * 16;
            uint32_t ah[4], al[4];
            ah[0] = *(const uint32_t*)(Ph + r0l * AST2 + kk + 2 * t4);
            ah[1] = *(const uint32_t*)(Ph + r1l * AST2 + kk + 2 * t4);
            ah[2] = *(const uint32_t*)(Ph + r0l * AST2 + kk + 2 * t4 + 8);
            ah[3] = *(const uint32_t*)(Ph + r1l * AST2 + kk + 2 * t4 + 8);
            al[0] = *(const uint32_t*)(Pl + r0l * AST2 + kk + 2 * t4);
            al[1] = *(const uint32_t*)(Pl + r1l * AST2 + kk + 2 * t4);
            al[2] = *(const uint32_t*)(Pl + r0l * AST2 + kk + 2 * t4 + 8);
            al[3] = *(const uint32_t*)(Pl + r1l * AST2 + kk + 2 * t4 + 8);
            uint32_t vaddr = vbase + (uint32_t)((kk + vRow) * AST2) * 2;
#pragma unroll
            for (int nt = 0; nt < 8; nt++) {
                uint32_t bf[2];
                ldsm_x2_trans(bf, vaddr + (uint32_t)(nt * 8) * 2);
                mma16(o[nt], ah, bf);
                mma16(o[nt], al, bf);
            }
        }

        __syncthreads();
        if (kt + 2 <= qt) load_kv(st, kt + 2);
    }

    float i0 = 1.f / l0, i1 = 1.f / l1;
    size_t row0 = (size_t)(b * Tt + qt * 64 + r0l) * Cd + h * HSd;
    size_t row1 = (size_t)(b * Tt + qt * 64 + r1l) * Cd + h * HSd;
#pragma unroll
    for (int nt = 0; nt < 8; nt++) {
        int c0 = nt * 8 + 2 * t4;
        *(__half2*)(O + row0 + c0) = __floats2half2_rn(o[nt][0] * i0, o[nt][1] * i0);
        *(__half2*)(O + row1 + c0) = __floats2half2_rn(o[nt][2] * i1, o[nt][3] * i1);
    }
}

// ---------------- loss kernels ----------------
__global__ void zero_kernel(float* p, int n) {
    int i = blockIdx.x * blockDim.x + threadIdx.x;
    if (i < n) p[i] = 0.f;
}

__global__ __launch_bounds__(256) void lossfinal_kernel(const float* __restrict__ ls,
                                                        const float* __restrict__ logits,
                                                        const int* __restrict__ tgt,
                                                        float* __restrict__ out) {
    float s = 0.f;
    for (int r = threadIdx.x; r < NT; r += 256)
        s += logf(ls[r]) - logits[(size_t)r * Vv + tgt[r]];
    s = blockReduceSum256(s);
    if (threadIdx.x == 0) out[0] = s * (1.0f / NT);
}

__global__ __launch_bounds__(256) void lossreduce_kernel(const float* __restrict__ rl,
                                                         float* __restrict__ out) {
    float s = 0.f;
    for (int i = threadIdx.x; i < NT; i += 256) s += rl[i];
    s = blockReduceSum256(s);
    if (threadIdx.x == 0) out[0] = s * (1.0f / NT);
}

__global__ void lse_init_kernel(float* lm, float* ls, float* lt) {
    int i = blockIdx.x * blockDim.x + threadIdx.x;
    if (i < NT) { lm[i] = -1e30f; ls[i] = 0.f; lt[i] = 0.f; }
}

__global__ __launch_bounds__(256) void chunkloss_kernel(const float* __restrict__ chunk,
                                                        int width, int col0,
                                                        const int* __restrict__ tgt,
                                                        float* __restrict__ lm,
                                                        float* __restrict__ ls,
                                                        float* __restrict__ lt) {
    int r = blockIdx.x;
    const float* cr = chunk + (size_t)r * width;
    float m = -1e30f;
    for (int c = threadIdx.x; c < width; c += 256) m = fmaxf(m, cr[c]);
    m = blockReduceMax256(m);
    float s = 0.f;
    for (int c = threadIdx.x; c < width; c += 256) s += __expf(cr[c] - m);
    s = blockReduceSum256(s);
    if (threadIdx.x == 0) {
        float mOld = lm[r];
        float mNew = fmaxf(mOld, m);
        ls[r] = ls[r] * __expf(mOld - mNew) + s * __expf(m - mNew);
        lm[r] = mNew;
        int tg = tgt[r] - col0;
        if (tg >= 0 && tg < width) lt[r] = cr[tg];
    }
}

__global__ void chunkfinal_kernel(const float* lm, const float* ls, const float* lt,
                                  float* rl) {
    int i = blockIdx.x * blockDim.x + threadIdx.x;
    if (i < NT) rl[i] = lm[i] + logf(ls[i]) - lt[i];
}

// ---------------- host driver ----------------
static void* devptr(const void* sym) {
    void* p = nullptr;
    cudaGetSymbolAddress(&p, sym);
    return p;
}

extern "C" void kernel_launch(void* const* d_in, const int* in_sizes, int n_in,
                              void* d_out, int out_size) {
    const int* inputs    = (const int*)d_in[0];
    const int* targets   = (const int*)d_in[1];
    const float* tok     = (const float*)d_in[2];
    const float* pos     = (const float*)d_in[3];
    const float* ln1g    = (const float*)d_in[4];
    const float* ln1b    = (const float*)d_in[5];
    const float* ln2g    = (const float*)d_in[6];
    const float* ln2b    = (const float*)d_in[7];
    const float* wq      = (const float*)d_in[8];
    const float* wk      = (const float*)d_in[9];
    const float* wv      = (const float*)d_in[10];
    const float* wo      = (const float*)d_in[11];
    const float* bo      = (const float*)d_in[12];
    const float* w1      = (const float*)d_in[13];
    const float* b1      = (const float*)d_in[14];
    const float* w2      = (const float*)d_in[15];
    const float* b2      = (const float*)d_in[16];
    const float* lnfg    = (const float*)d_in[17];
    const float* lnfb    = (const float*)d_in[18];
    const float* whead   = (const float*)d_in[19];
    const float* bhead   = (const float*)d_in[20];

    float*  x   = (float*)devptr(g_x);
    __half* h   = (__half*)devptr(g_h);
    __half* qkv = (__half*)devptr(g_qkv);
    __half* ob  = (__half*)devptr(g_ob);
    __half* fb  = (__half*)devptr(g_f);
    float*  rl  = (float*)devptr(g_rowloss);
    float*  lm  = (float*)devptr(g_lm);
    float*  ls  = (float*)devptr(g_ls);
    float*  lt  = (float*)devptr(g_lt);
    __half* wth = (__half*)devptr(g_wth);

    cudaFuncSetAttribute(mma_gemm<false, false, false, false, true, false>, cudaFuncAttributeMaxDynamicSharedMemorySize, GEMM_SMEM);
    cudaFuncSetAttribute(mma_gemm<true, false, true, false, false, false>,  cudaFuncAttributeMaxDynamicSharedMemorySize, GEMM_SMEM);
    cudaFuncSetAttribute(mma_gemm<true, true, false, false, true, false>,   cudaFuncAttributeMaxDynamicSharedMemorySize, GEMM_SMEM);
    cudaFuncSetAttribute(mma_gemm<true, false, false, true, false, true>,   cudaFuncAttributeMaxDynamicSharedMemorySize, GEMM_SMEM);
    cudaFuncSetAttribute(mma_gemm<true, false, false, true, false, false>,  cudaFuncAttributeMaxDynamicSharedMemorySize, GEMM_SMEM);
    cudaFuncSetAttribute(attn_tc_kernel, cudaFuncAttributeMaxDynamicSharedMemorySize, ATTN_SMEM);

    // ---- weight prep: fp16 convert + transpose to [N][K], once per launch ----
    {
        dim3 blk(256);
        size_t cc = (size_t)Cd * Cd, cf = (size_t)Cd * Fd;
        dim3 gCC(Cd / 32, Cd / 64, Ll);
        transpose_h_kernel<<<gCC, blk>>>(wq, wth + OFF_QKV + (size_t)0 * cc, Cd, Cd, Cd, cc, (size_t)QKVS * Cd);
        transpose_h_kernel<<<gCC, blk>>>(wk, wth + OFF_QKV + (size_t)1 * cc, Cd, Cd, Cd, cc, (size_t)QKVS * Cd);
        transpose_h_kernel<<<gCC, blk>>>(wv, wth + OFF_QKV + (size_t)2 * cc, Cd, Cd, Cd, cc, (size_t)QKVS * Cd);
        transpose_h_kernel<<<gCC, blk>>>(wo, wth + OFF_WO, Cd, Cd, Cd, cc, cc);
        dim3 gW1(Fd / 32, Cd / 64, Ll);
        transpose_h_kernel<<<gW1, blk>>>(w1, wth + OFF_W1, Cd, Fd, Fd, cf, cf);
        dim3 gW2(Cd / 32, Fd / 64, Ll);
        transpose_h_kernel<<<gW2, blk>>>(w2, wth + OFF_W2, Fd, Cd, Cd, cf, cf);
        dim3 gHd(VPAD / 32, Cd / 64, 1);
        transpose_h_kernel<<<gHd, blk>>>(whead, wth + OFF_HD, Cd, Vv, VPAD, 0, 0);
    }

    dim3 gAttn(Tt / 64, Bq * Hh);

    embed_kernel<<<NT, 192>>>(inputs, tok, pos, x);

    for (int l = 0; l < Ll; l++) {
        const __half* wqkv = wth + OFF_QKV + (size_t)l * Cd * QKVS;
        const __half* wot  = wth + OFF_WO + (size_t)l * Cd * Cd;
        const __half* w1t  = wth + OFF_W1 + (size_t)l * Cd * Fd;
        const __half* w2t  = wth + OFF_W2 + (size_t)l * Fd * Cd;

        ln_kernel<<<NT / 8, 256>>>(x, ln1g + l * Cd, ln1b + l * Cd, h);
        mma_gemm<false, false, false, false, true, false><<<GEMM_GRID, 256, GEMM_SMEM>>>(
            h, wqkv, nullptr, nullptr, qkv, NT, QKVS, Cd, QKVS / 128, nullptr);
        attn_tc_kernel<<<gAttn, 128, ATTN_SMEM>>>(qkv, ob);
        mma_gemm<true, false, true, false, false, false><<<GEMM_GRID, 256, GEMM_SMEM>>>(
            ob, wot, bo + l * Cd, x, x, NT, Cd, Cd, Cd / 128, nullptr);
        ln_kernel<<<NT / 8, 256>>>(x, ln2g + l * Cd, ln2b + l * Cd, h);
        mma_gemm<true, true, false, false, true, false><<<GEMM_GRID, 256, GEMM_SMEM>>>(
            h, w1t, b1 + (size_t)l * Fd, nullptr, fb, NT, Fd, Cd, Fd / 128, nullptr);
        mma_gemm<true, false, true, false, false, false><<<GEMM_GRID, 256, GEMM_SMEM>>>(
            fb, w2t, b2 + l * Cd, x, x, NT, Cd, Fd, Cd / 128, nullptr);
    }

    ln_kernel<<<NT / 8, 256>>>(x, lnfg, lnfb, h);

    const long long NV = (long long)NT * Vv;
    if ((long long)out_size >= NV) {
        float* logits = (float*)d_out;
        bool wantLoss = ((long long)out_size > NV);
        if (wantLoss) {
            zero_kernel<<<(NT + 255) / 256, 256>>>(ls, NT);
            mma_gemm<true, false, false, true, false, true><<<GEMM_GRID, 256, GEMM_SMEM>>>(
                h, wth + OFF_HD, bhead, nullptr, logits, NT, Vv, Cd, VPAD / 128, ls);
            lossfinal_kernel<<<1, 256>>>(ls, logits, targets, (float*)d_out + NV);
        } else {
            mma_gemm<true, false, false, true, false, false><<<GEMM_GRID, 256, GEMM_SMEM>>>(
                h, wth + OFF_HD, bhead, nullptr, logits, NT, Vv, Cd, VPAD / 128, nullptr);
        }
    } else {
        h2f_kernel<<<2048, 256>>>(h, x, (size_t)NT * Cd);
        lse_init_kernel<<<(NT + 255) / 256, 256>>>(lm, ls, lt);
        const int CW = 3072;
        float* fbuf = (float*)devptr(g_f);
        for (int col0 = 0; col0 < Vv; col0 += CW) {
            int width = (Vv - col0 < CW) ? (Vv - col0) : CW;
            dim3 gCk(NT / 128, (width + 63) / 64);
            sgemm_kernel<true, false, false><<<gCk, 256>>>(x, whead + col0, bhead + col0,
                                                           nullptr, fbuf, NT, width, Cd, Vv);
            chunkloss_kernel<<<NT, 256>>>(fbuf, width, col0, targets, lm, ls, lt);
        }
        chunkfinal_kernel<<<(NT + 255) / 256, 256>>>(lm, ls, lt, rl);
        lossreduce_kernel<<<1, 256>>>(rl, (float*)d_out);
    }
}

// round 17
// speedup vs baseline: 1.0149x; 1.0149x over previous
#include <cuda_runtime.h>
#include <cuda_fp16.h>
#include <math.h>
#include <stdint.h>

// ---------------- problem constants (GPT-2 small forward) ----------------
#define Bq   8
#define Tt   1024
#define NT   8192          // B*T tokens
#define Cd   768
#define Hh   12
#define HSd  64
#define Fd   3072
#define Ll   12
#define Vv   50257
#define VPAD 50304         // multiple of 128
#define QKVS 2304          // fused qkv width
#define GEMM_GRID 304      // ~2 CTAs/SM on 152 SMs

// ---------------- scratch (device globals: allocation-free) --------------
__device__ float  g_x[(size_t)NT * Cd];        // residual stream (fp32)
__device__ __half g_h[(size_t)NT * Cd];        // LN output (fp16)
__device__ __half g_qkv[(size_t)NT * QKVS];    // fused q|k|v (fp16)
__device__ __half g_ob[(size_t)NT * Cd];       // attention out (fp16)
__device__ __half g_f[(size_t)NT * Fd];        // MLP hidden (fp16)
__device__ float  g_rowloss[NT];
__device__ float  g_lm[NT];
__device__ float  g_ls[NT];
__device__ float  g_lt[NT];

// fp16 weights, pre-transposed to [N][K] (K-contiguous)
#define OFF_QKV ((size_t)0)                        // [L][2304][768]
#define OFF_WO  ((size_t)21233664)                 // [L][768][768]
#define OFF_W1  ((size_t)28311552)                 // [L][3072][768]
#define OFF_W2  ((size_t)56623104)                 // [L][768][3072]
#define OFF_HD  ((size_t)84934656)                 // [VPAD][768]
#define WTH_TOTAL ((size_t)84934656 + (size_t)VPAD * Cd)
__device__ __half g_wth[WTH_TOTAL];

// ---------------- helpers ----------------
__device__ __forceinline__ uint32_t smem_u32(const void* p) {
    uint32_t a;
    asm("{ .reg .u64 t; cvta.to.shared.u64 t, %1; cvt.u32.u64 %0, t; }" : "=r"(a) : "l"(p));
    return a;
}

__device__ __forceinline__ void cp16(uint32_t saddr, const void* gaddr) {
    asm volatile("cp.async.cg.shared.global [%0], [%1], 16;" :: "r"(saddr), "l"(gaddr));
}
#define CP_COMMIT() asm volatile("cp.async.commit_group;" ::: "memory")
#define CP_WAIT1()  asm volatile("cp.async.wait_group 1;" ::: "memory")
#define CP_WAIT0()  asm volatile("cp.async.wait_group 0;" ::: "memory")

__device__ __forceinline__ void mma16(float* c, const uint32_t* a, const uint32_t* b) {
    asm volatile(
        "mma.sync.aligned.m16n8k16.row.col.f32.f16.f16.f32 "
        "{%0,%1,%2,%3}, {%4,%5,%6,%7}, {%8,%9}, {%0,%1,%2,%3};\n"
        : "+f"(c[0]), "+f"(c[1]), "+f"(c[2]), "+f"(c[3])
        : "r"(a[0]), "r"(a[1]), "r"(a[2]), "r"(a[3]), "r"(b[0]), "r"(b[1]));
}

__device__ __forceinline__ void ldsm_x4(uint32_t* r, uint32_t saddr) {
    asm volatile("ldmatrix.sync.aligned.m8n8.x4.shared.b16 {%0,%1,%2,%3}, [%4];"
                 : "=r"(r[0]), "=r"(r[1]), "=r"(r[2]), "=r"(r[3]) : "r"(saddr));
}
__device__ __forceinline__ void ldsm_x2_trans(uint32_t* r, uint32_t saddr) {
    asm volatile("ldmatrix.sync.aligned.m8n8.x2.trans.shared.b16 {%0,%1}, [%2];"
                 : "=r"(r[0]), "=r"(r[1]) : "r"(saddr));
}

// ---------------- block reduce helpers ----------------
__device__ __forceinline__ float blockReduceSum256(float v) {
    __shared__ float sh[8];
    int lane = threadIdx.x & 31, w = threadIdx.x >> 5;
#pragma unroll
    for (int o = 16; o; o >>= 1) v += __shfl_xor_sync(0xffffffffu, v, o);
    if (lane == 0) sh[w] = v;
    __syncthreads();
    float r = (threadIdx.x < 8) ? sh[threadIdx.x] : 0.f;
    if (w == 0) {
#pragma unroll
        for (int o = 4; o; o >>= 1) r += __shfl_xor_sync(0xffffffffu, r, o);
    }
    __syncthreads();
    if (threadIdx.x == 0) sh[0] = r;
    __syncthreads();
    return sh[0];
}

__device__ __forceinline__ float blockReduceMax256(float v) {
    __shared__ float sh[8];
    int lane = threadIdx.x & 31, w = threadIdx.x >> 5;
#pragma unroll
    for (int o = 16; o; o >>= 1) v = fmaxf(v, __shfl_xor_sync(0xffffffffu, v, o));
    if (lane == 0) sh[w] = v;
    __syncthreads();
    float r = (threadIdx.x < 8) ? sh[threadIdx.x] : -1e30f;
    if (w == 0) {
#pragma unroll
        for (int o = 4; o; o >>= 1) r = fmaxf(r, __shfl_xor_sync(0xffffffffu, r, o));
    }
    __syncthreads();
    if (threadIdx.x == 0) sh[0] = r;
    __syncthreads();
    return sh[0];
}

// ---------------- weight prep: transpose f32 [K][N] -> fp16 [Npad][K] -----
__global__ __launch_bounds__(256) void transpose_h_kernel(
    const float* __restrict__ src, __half* __restrict__ dst,
    int K, int N, int Npad, size_t sstride, size_t dstride) {
    src += (size_t)blockIdx.z * sstride;
    dst += (size_t)blockIdx.z * dstride;
    __shared__ float t[64][33];
    const int kb = blockIdx.y * 64, nb = blockIdx.x * 32;
    const int warp = threadIdx.x >> 5, lane = threadIdx.x & 31;
#pragma unroll
    for (int j = 0; j < 8; j++) {
        int r = warp * 8 + j;
        int k = kb + r, n = nb + lane;
        t[r][lane] = (k < K && n < N) ? src[(size_t)k * N + n] : 0.f;
    }
    __syncthreads();
#pragma unroll
    for (int j = 0; j < 4; j++) {
        int nl = warp * 4 + j;
        int n = nb + nl;
        int k = kb + lane * 2;
        if (n < Npad && k < K) {
            __half2 v = __floats2half2_rn(t[lane * 2][nl], t[lane * 2 + 1][nl]);
            *(__half2*)(dst + (size_t)n * K + k) = v;
        }
    }
}

// =====================================================================
// fp16 mma.sync GEMM (persistent): C[M,Nn] = A[M,K](fp16) @ Wt[N][K]^T
// BM=128, BN=128, BK=64, 256 threads; cp.async 3-stage; ldmatrix x4 loads.
// Prefetch interleaved: A-loads after ks=0, B-loads+commit after ks=1.
// LSE: accumulate per-row sum(exp(logit)) into lse[] via atomics.
// =====================================================================
#define ASTH 72
#define HTILE_H (128 * ASTH)            // 9216 halfs
#define HSTG_H  (2 * HTILE_H)           // A + B
#define NSTG 3
#define GEMM_SMEM (NSTG * HSTG_H * 2)   // 110592 bytes

template<bool BIAS, bool RELU, bool RES, bool NBOUND, bool OUTH, bool LSE>
__global__ __launch_bounds__(256, 2) void mma_gemm(
    const __half* __restrict__ A, const __half* __restrict__ Wt,
    const float* __restrict__ bias, const float* __restrict__ res,
    void* __restrict__ Cv, int M, int Nn, int K, int ntn,
    float* __restrict__ lse) {
    extern __shared__ __half smh[];
    const uint32_t su = smem_u32(smh);
    const int tid = threadIdx.x;
    const int warp = tid >> 5, lane = tid & 31;
    const int g = lane >> 2, t4 = lane & 3;
    const int wm = warp >> 2, wn = warp & 3;
    const int warp_m0 = wm * 64, warp_n0 = wn * 32;

    const int mA = lane >> 3;
    const int aRow = (mA & 1) * 8 + (lane & 7);
    const int aCol = (mA >> 1) * 8;
    uint32_t offA[4];
#pragma unroll
    for (int mt = 0; mt < 4; mt++)
        offA[mt] = (uint32_t)((warp_m0 + mt * 16 + aRow) * ASTH + aCol);
    const int tIdx = lane >> 3;
    const int bRowAdd = (tIdx >> 1) * 8 + (lane & 7);
    const int bColAdd = (tIdx & 1) * 8;
    uint32_t offB2[2];
#pragma unroll
    for (int nt2 = 0; nt2 < 2; nt2++)
        offB2[nt2] = (uint32_t)(HTILE_H + (warp_n0 + nt2 * 16 + bRowAdd) * ASTH + bColAdd);

    const int nk = K >> 6;
    const int ntm = M >> 7;
    const int ntiles = ntm * ntn;

    for (int tile = blockIdx.x; tile < ntiles; tile += gridDim.x) {
        const int m0 = (tile % ntm) * 128;
        const int n0 = (tile / ntm) * 128;
        __syncthreads();   // guard smem reuse across tiles

        float acc[4][4][4];
#pragma unroll
        for (int mt = 0; mt < 4; mt++)
#pragma unroll
            for (int nt = 0; nt < 4; nt++)
#pragma unroll
                for (int j = 0; j < 4; j++) acc[mt][nt][j] = 0.f;

        auto load_A = [&](int s, int kb) {
            uint32_t sa = su + (uint32_t)s * HSTG_H * 2;
#pragma unroll
            for (int i = 0; i < 4; i++) {
                int ch = tid + i * 256;
                int r = ch >> 3, c = ch & 7;
                cp16(sa + (uint32_t)(r * ASTH + c * 8) * 2,
                     A + (size_t)(m0 + r) * K + kb + c * 8);
            }
        };
        auto load_B = [&](int s, int kb) {
            uint32_t sb = su + (uint32_t)s * HSTG_H * 2 + HTILE_H * 2;
#pragma unroll
            for (int i = 0; i < 4; i++) {
                int ch = tid + i * 256;
                int r = ch >> 3, c = ch & 7;
                cp16(sb + (uint32_t)(r * ASTH + c * 8) * 2,
                     Wt + (size_t)(n0 + r) * K + kb + c * 8);
            }
        };

        load_A(0, 0);  load_B(0, 0);  CP_COMMIT();
        load_A(1, 64); load_B(1, 64); CP_COMMIT();

        int s = 0;
        for (int kc = 0; kc < nk; kc++) {
            if (kc + 1 < nk) CP_WAIT1(); else CP_WAIT0();
            __syncthreads();

            const bool pf = (kc + 2 < nk);
            int sw = s + 2; if (sw >= NSTG) sw -= NSTG;
            const int kb2 = (kc + 2) * 64;

            const uint32_t sbase = su + (uint32_t)s * HSTG_H * 2;
#pragma unroll
            for (int ks = 0; ks < 4; ks++) {
                const int kk = ks * 16;
                uint32_t af[4][4], bf[4][2];
#pragma unroll
                for (int mt = 0; mt < 4; mt++)
                    ldsm_x4(af[mt], sbase + (offA[mt] + kk) * 2);
#pragma unroll
                for (int nt2 = 0; nt2 < 2; nt2++) {
                    uint32_t bt[4];
                    ldsm_x4(bt, sbase + (offB2[nt2] + kk) * 2);
                    bf[nt2 * 2 + 0][0] = bt[0]; bf[nt2 * 2 + 0][1] = bt[1];
                    bf[nt2 * 2 + 1][0] = bt[2]; bf[nt2 * 2 + 1][1] = bt[3];
                }
#pragma unroll
                for (int mt = 0; mt < 4; mt++)
#pragma unroll
                    for (int nt = 0; nt < 4; nt++)
                        mma16(acc[mt][nt], af[mt], bf[nt]);

                // interleaved prefetch: after ks=0's fragments/MMAs are issued,
                // the LSU is free — inject global loads under the MMA shadow.
                if (ks == 0 && pf) load_A(sw, kb2);
                if (ks == 1 && pf) { load_B(sw, kb2); CP_COMMIT(); }
            }

            if (++s == NSTG) s = 0;
        }

        // ---- epilogue ----
        float rowsum[4][2];
        if (LSE) {
#pragma unroll
            for (int mt = 0; mt < 4; mt++) { rowsum[mt][0] = 0.f; rowsum[mt][1] = 0.f; }
        }
#pragma unroll
        for (int mt = 0; mt < 4; mt++) {
            int r0 = m0 + warp_m0 + mt * 16 + g;
#pragma unroll
            for (int nt = 0; nt < 4; nt++) {
                int cn = n0 + warp_n0 + nt * 8 + t4 * 2;
                float* a4 = acc[mt][nt];
                float b0 = 0.f, b1 = 0.f;
                if (BIAS) {
                    if (!NBOUND) { b0 = bias[cn]; b1 = bias[cn + 1]; }
                    else {
                        b0 = (cn < Nn) ? bias[cn] : 0.f;
                        b1 = (cn + 1 < Nn) ? bias[cn + 1] : 0.f;
                    }
                }
#pragma unroll
                for (int half_ = 0; half_ < 2; half_++) {
                    int r = r0 + half_ * 8;
                    float v0 = a4[half_ * 2 + 0] + b0;
                    float v1 = a4[half_ * 2 + 1] + b1;
                    if (RELU) { v0 = fmaxf(v0, 0.f); v1 = fmaxf(v1, 0.f); }
                    size_t off = (size_t)r * Nn + cn;
                    if (!NBOUND) {
                        if (RES) { v0 += res[off]; v1 += res[off + 1]; }
                        if (OUTH) {
                            *(__half2*)((__half*)Cv + off) = __floats2half2_rn(v0, v1);
                        } else {
                            *(float2*)((float*)Cv + off) = make_float2(v0, v1);
                        }
                    } else {
                        float* C = (float*)Cv;
                        if (cn < Nn) {
                            if (RES) v0 += res[off];
                            C[off] = v0;
                            if (LSE) rowsum[mt][half_] += __expf(v0);
                        }
                        if (cn + 1 < Nn) {
                            if (RES) v1 += res[off + 1];
                            C[off + 1] = v1;
                            if (LSE) rowsum[mt][half_] += __expf(v1);
                        }
                    }
                }
            }
        }
        if (LSE) {
#pragma unroll
            for (int mt = 0; mt < 4; mt++) {
#pragma unroll
                for (int half_ = 0; half_ < 2; half_++) {
                    float sc = rowsum[mt][half_];
                    sc += __shfl_xor_sync(0xffffffffu, sc, 1);
                    sc += __shfl_xor_sync(0xffffffffu, sc, 2);
                    if (t4 == 0) {
                        int r = m0 + warp_m0 + mt * 16 + g + half_ * 8;
                        atomicAdd(&lse[r], sc);
                    }
                }
            }
        }
    }
}

// ---------------- embedding (float4 vectorized) ----------------
__global__ void embed_kernel(const int* __restrict__ inp,
                             const float* __restrict__ tok,
                             const float* __restrict__ pos,
                             float* __restrict__ x) {
    int i = blockIdx.x;
    int t = i & (Tt - 1);
    int v = inp[i];
    const float4* te = (const float4*)(tok + (size_t)v * Cd);
    const float4* pe = (const float4*)(pos + (size_t)t * Cd);
    float4* xo = (float4*)(x + (size_t)i * Cd);
    for (int c = threadIdx.x; c < Cd / 4; c += blockDim.x) {
        float4 a = te[c], b = pe[c];
        a.x += b.x; a.y += b.y; a.z += b.z; a.w += b.w;
        xo[c] = a;
    }
}

// ---------------- layernorm: warp per row, fp16 output ----------------
__global__ __launch_bounds__(256) void ln_kernel(const float* __restrict__ x,
                                                 const float* __restrict__ g,
                                                 const float* __restrict__ b,
                                                 __half* __restrict__ out) {
    const int warp = threadIdx.x >> 5, lane = threadIdx.x & 31;
    const int row = blockIdx.x * 8 + warp;
    const float4* xr = (const float4*)(x + (size_t)row * Cd);
    const float4* gp = (const float4*)g;
    const float4* bp = (const float4*)b;
    __half* orow = out + (size_t)row * Cd;

    float4 v[6];
    float s = 0.f;
#pragma unroll
    for (int i = 0; i < 6; i++) {
        v[i] = xr[lane + i * 32];
        s += v[i].x + v[i].y + v[i].z + v[i].w;
    }
#pragma unroll
    for (int o = 16; o; o >>= 1) s += __shfl_xor_sync(0xffffffffu, s, o);
    float mean = s * (1.0f / Cd);

    float vs = 0.f;
#pragma unroll
    for (int i = 0; i < 6; i++) {
        float dx = v[i].x - mean, dy = v[i].y - mean,
              dz = v[i].z - mean, dw = v[i].w - mean;
        vs += dx * dx + dy * dy + dz * dz + dw * dw;
    }
#pragma unroll
    for (int o = 16; o; o >>= 1) vs += __shfl_xor_sync(0xffffffffu, vs, o);
    float rstd = rsqrtf(vs * (1.0f / Cd) + 1e-5f);

#pragma unroll
    for (int i = 0; i < 6; i++) {
        float4 gg = gp[lane + i * 32];
        float4 bb = bp[lane + i * 32];
        __half2 h01 = __floats2half2_rn((v[i].x - mean) * rstd * gg.x + bb.x,
                                        (v[i].y - mean) * rstd * gg.y + bb.y);
        __half2 h23 = __floats2half2_rn((v[i].z - mean) * rstd * gg.z + bb.z,
                                        (v[i].w - mean) * rstd * gg.w + bb.w);
        uint2 pk = make_uint2(*(uint32_t*)&h01, *(uint32_t*)&h23);
        *(uint2*)(orow + (lane + i * 32) * 4) = pk;
    }
}

// ---------------- fp16 -> fp32 convert (fallback path) ----------------
__global__ void h2f_kernel(const __half* __restrict__ src, float* __restrict__ dst, size_t n) {
    for (size_t i = (size_t)blockIdx.x * blockDim.x + threadIdx.x; i < n;
         i += (size_t)gridDim.x * blockDim.x)
        dst[i] = __half2float(src[i]);
}

// ---------------- SIMT SGEMM (loss-only fallback path) ----------------
template<bool BIAS, bool RELU, bool RES>
__global__ __launch_bounds__(256) void sgemm_kernel(
    const float* __restrict__ A, const float* __restrict__ W,
    const float* __restrict__ bias, const float* __restrict__ res,
    float* __restrict__ Cout, int M, int Nn, int K, int ldw) {
    __shared__ float As[16][132];
    __shared__ float Bs[16][64];
    int tid = threadIdx.x;
    int m0 = blockIdx.x * 128;
    int n0 = blockIdx.y * 64;
    int tx = tid & 15, ty = tid >> 4;
    float acc[8][4];
#pragma unroll
    for (int i = 0; i < 8; i++)
#pragma unroll
        for (int j = 0; j < 4; j++) acc[i][j] = 0.f;
    int am = tid >> 1;
    int ak = (tid & 1) * 8;
    int bk = tid >> 4;
    int bn = (tid & 15) * 4;
    for (int k0 = 0; k0 < K; k0 += 16) {
        const float* Ap = A + (size_t)(m0 + am) * K + k0 + ak;
        float4 a0 = *(const float4*)Ap;
        float4 a1 = *(const float4*)(Ap + 4);
        As[ak + 0][am] = a0.x; As[ak + 1][am] = a0.y;
        As[ak + 2][am] = a0.z; As[ak + 3][am] = a0.w;
        As[ak + 4][am] = a1.x; As[ak + 5][am] = a1.y;
        As[ak + 6][am] = a1.z; As[ak + 7][am] = a1.w;
        int gn = n0 + bn;
        const float* Wp = W + (size_t)(k0 + bk) * ldw + gn;
        float4 bv;
        bv.x = (gn + 0 < Nn) ? Wp[0] : 0.f;
        bv.y = (gn + 1 < Nn) ? Wp[1] : 0.f;
        bv.z = (gn + 2 < Nn) ? Wp[2] : 0.f;
        bv.w = (gn + 3 < Nn) ? Wp[3] : 0.f;
        *(float4*)&Bs[bk][bn] = bv;
        __syncthreads();
#pragma unroll
        for (int kk = 0; kk < 16; kk++) {
            float4 a04 = *(const float4*)&As[kk][ty * 8];
            float4 a14 = *(const float4*)&As[kk][ty * 8 + 4];
            float4 b4  = *(const float4*)&Bs[kk][tx * 4];
            float a[8] = {a04.x, a04.y, a04.z, a04.w, a14.x, a14.y, a14.z, a14.w};
            float bb[4] = {b4.x, b4.y, b4.z, b4.w};
#pragma unroll
            for (int i = 0; i < 8; i++)
#pragma unroll
                for (int j = 0; j < 4; j++)
                    acc[i][j] += a[i] * bb[j];
        }
        __syncthreads();
    }
    int nbase = n0 + tx * 4;
#pragma unroll
    for (int i = 0; i < 8; i++) {
        size_t rowoff = (size_t)(m0 + ty * 8 + i) * Nn;
#pragma unroll
        for (int j = 0; j < 4; j++) {
            int n = nbase + j;
            if (n < Nn) {
                float v = acc[i][j];
                if (BIAS) v += bias[n];
                if (RELU) v = fmaxf(v, 0.f);
                if (RES) v += res[rowoff + n];
                Cout[rowoff + n] = v;
            }
        }
    }
}

// =====================================================================
// fp16 tensor-core flash attention (S exact; P split hi/lo fp16)
// cp.async double-buffered K/V tiles (row-major [j][d]); V via ldmatrix.trans
// =====================================================================
#define AST2 72
#define ATILE (64 * AST2)
#define ATTN_SMEM (6 * ATILE * 2)   // 55296 bytes

__global__ __launch_bounds__(128, 4) void attn_tc_kernel(const __half* __restrict__ QKV,
                                                         __half* __restrict__ O) {
    extern __shared__ __half sme[];
    __half* Ks0 = sme;
    __half* Vs0 = Ks0 + ATILE;
    __half* Ks1 = Vs0 + ATILE;
    __half* Vs1 = Ks1 + ATILE;
    __half* Ph  = Vs1 + ATILE;
    __half* Pl  = Ph + ATILE;
    const uint32_t suK[2] = { smem_u32(Ks0), smem_u32(Ks1) };

    const int qt = gridDim.x - 1 - blockIdx.x;
    const int bh = blockIdx.y;
    const int b = bh / Hh, h = bh % Hh;
    const int tid = threadIdx.x;
    const int warp = tid >> 5, lane = tid & 31;
    const int g = lane >> 2, t4 = lane & 3;
    const int r0l = warp * 16 + g;
    const int r1l = r0l + 8;

    auto load_kv = [&](int stage, int kt) {
        uint32_t sk = suK[stage];
        const __half* base = QKV + (size_t)(b * Tt + kt * 64) * QKVS + h * HSd;
#pragma unroll
        for (int i = 0; i < 4; i++) {
            int ch = tid + i * 128;
            int r = ch >> 3, c8 = (ch & 7) * 8;
            const __half* grow = base + (size_t)r * QKVS + c8;
            cp16(sk + (uint32_t)(r * AST2 + c8) * 2, grow + Cd);
            cp16(sk + (uint32_t)(ATILE + r * AST2 + c8) * 2, grow + 2 * Cd);
        }
        CP_COMMIT();
    };

    load_kv(0, 0);
    if (qt >= 1) load_kv(1, 1);

#pragma unroll
    for (int i = 0; i < 4; i++) {
        int ch = tid + i * 128;
        int r = ch >> 3, c8 = (ch & 7) * 8;
        float4 v = *(const float4*)(QKV + (size_t)(b * Tt + qt * 64 + r) * QKVS + h * HSd + c8);
        *(float4*)(Ph + r * AST2 + c8) = v;
    }
    __syncthreads();

    uint32_t qf[4][4];
#pragma unroll
    for (int ks = 0; ks < 4; ks++) {
        int kk = ks * 16;
        qf[ks][0] = *(const uint32_t*)(Ph + r0l * AST2 + kk + 2 * t4);
        qf[ks][1] = *(const uint32_t*)(Ph + r1l * AST2 + kk + 2 * t4);
        qf[ks][2] = *(const uint32_t*)(Ph + r0l * AST2 + kk + 2 * t4 + 8);
        qf[ks][3] = *(const uint32_t*)(Ph + r1l * AST2 + kk + 2 * t4 + 8);
    }

    const int vRow = (lane & 7) + ((lane >> 3) & 1) * 8;

    float o[8][4];
#pragma unroll
    for (int nt = 0; nt < 8; nt++)
#pragma unroll
        for (int j = 0; j < 4; j++) o[nt][j] = 0.f;
    float m0 = -1e30f, m1 = -1e30f, l0 = 0.f, l1 = 0.f;

    for (int kt = 0; kt <= qt; kt++) {
        const int st = kt & 1;
        if (kt < qt) CP_WAIT1(); else CP_WAIT0();
        __syncthreads();

        const __half* Ks = (st == 0) ? Ks0 : Ks1;
        const uint32_t vbase = suK[st] + ATILE * 2;

        float sacc[8][4];
#pragma unroll
        for (int nt = 0; nt < 8; nt++)
#pragma unroll
            for (int j = 0; j < 4; j++) sacc[nt][j] = 0.f;
#pragma unroll
        for (int ks = 0; ks < 4; ks++) {
            int kk = ks * 16;
#pragma unroll
            for (int nt = 0; nt < 8; nt++) {
                int j = nt * 8 + g;
                uint32_t bf[2];
                bf[0] = *(const uint32_t*)(Ks + j * AST2 + kk + 2 * t4);
                bf[1] = *(const uint32_t*)(Ks + j * AST2 + kk + 2 * t4 + 8);
                mma16(sacc[nt], qf[ks], bf);
            }
        }
#pragma unroll
        for (int nt = 0; nt < 8; nt++)
#pragma unroll
            for (int j = 0; j < 4; j++) sacc[nt][j] *= 0.125f;

        if (kt == qt) {
#pragma unroll
            for (int nt = 0; nt < 8; nt++) {
                int c0 = nt * 8 + 2 * t4;
                if (c0     > r0l) sacc[nt][0] = -1e30f;
                if (c0 + 1 > r0l) sacc[nt][1] = -1e30f;
                if (c0     > r1l) sacc[nt][2] = -1e30f;
                if (c0 + 1 > r1l) sacc[nt][3] = -1e30f;
            }
        }

        float tm0 = -1e30f, tm1 = -1e30f;
#pragma unroll
        for (int nt = 0; nt < 8; nt++) {
            tm0 = fmaxf(tm0, fmaxf(sacc[nt][0], sacc[nt][1]));
            tm1 = fmaxf(tm1, fmaxf(sacc[nt][2], sacc[nt][3]));
        }
        tm0 = fmaxf(tm0, __shfl_xor_sync(0xffffffffu, tm0, 1));
        tm0 = fmaxf(tm0, __shfl_xor_sync(0xffffffffu, tm0, 2));
        tm1 = fmaxf(tm1, __shfl_xor_sync(0xffffffffu, tm1, 1));
        tm1 = fmaxf(tm1, __shfl_xor_sync(0xffffffffu, tm1, 2));
        float mN0 = fmaxf(m0, tm0), mN1 = fmaxf(m1, tm1);
        float a0 = __expf(m0 - mN0), a1 = __expf(m1 - mN1);
        m0 = mN0; m1 = mN1;

        float sum0 = 0.f, sum1 = 0.f;
#pragma unroll
        for (int nt = 0; nt < 8; nt++) {
            float p0 = __expf(sacc[nt][0] - mN0);
            float p1 = __expf(sacc[nt][1] - mN0);
            float p2 = __expf(sacc[nt][2] - mN1);
            float p3 = __expf(sacc[nt][3] - mN1);
            sum0 += p0 + p1;
            sum1 += p2 + p3;
            int c0 = nt * 8 + 2 * t4;
            __half2 h01 = __floats2half2_rn(p0, p1);
            __half2 h23 = __floats2half2_rn(p2, p3);
            *(__half2*)(Ph + r0l * AST2 + c0) = h01;
            *(__half2*)(Ph + r1l * AST2 + c0) = h23;
            *(__half2*)(Pl + r0l * AST2 + c0) =
                __floats2half2_rn(p0 - __half2float(__low2half(h01)),
                                  p1 - __half2float(__high2half(h01)));
            *(__half2*)(Pl + r1l * AST2 + c0) =
                __floats2half2_rn(p2 - __half2float(__low2half(h23)),
                                  p3 - __half2float(__high2half(h23)));
        }
        sum0 += __shfl_xor_sync(0xffffffffu, sum0, 1);
        sum0 += __shfl_xor_sync(0xffffffffu, sum0, 2);
        sum1 += __shfl_xor_sync(0xffffffffu, sum1, 1);
        sum1 += __shfl_xor_sync(0xffffffffu, sum1, 2);
        l0 = l0 * a0 + sum0;
        l1 = l1 * a1 + sum1;
#pragma unroll
        for (int nt = 0; nt < 8; nt++) {
            o[nt][0] *= a0; o[nt][1] *= a0;
            o[nt][2] *= a1; o[nt][3] *= a1;
        }
        __syncwarp();

#pragma unroll
        for (int ks = 0; ks < 4; ks++) {
            int kk = ks * 16;
            uint32_t ah[4], al[4];
            ah[0] = *(const uint32_t*)(Ph + r0l * AST2 + kk + 2 * t4);
            ah[1] = *(const uint32_t*)(Ph + r1l * AST2 + kk + 2 * t4);
            ah[2] = *(const uint32_t*)(Ph + r0l * AST2 + kk + 2 * t4 + 8);
            ah[3] = *(const uint32_t*)(Ph + r1l * AST2 + kk + 2 * t4 + 8);
            al[0] = *(const uint32_t*)(Pl + r0l * AST2 + kk + 2 * t4);
            al[1] = *(const uint32_t*)(Pl + r1l * AST2 + kk + 2 * t4);
            al[2] = *(const uint32_t*)(Pl + r0l * AST2 + kk + 2 * t4 + 8);
            al[3] = *(const uint32_t*)(Pl + r1l * AST2 + kk + 2 * t4 + 8);
            uint32_t vaddr = vbase + (uint32_t)((kk + vRow) * AST2) * 2;
#pragma unroll
            for (int nt = 0; nt < 8; nt++) {
                uint32_t bf[2];
                ldsm_x2_trans(bf, vaddr + (uint32_t)(nt * 8) * 2);
                mma16(o[nt], ah, bf);
                mma16(o[nt], al, bf);
            }
        }

        __syncthreads();
        if (kt + 2 <= qt) load_kv(st, kt + 2);
    }

    float i0 = 1.f / l0, i1 = 1.f / l1;
    size_t row0 = (size_t)(b * Tt + qt * 64 + r0l) * Cd + h * HSd;
    size_t row1 = (size_t)(b * Tt + qt * 64 + r1l) * Cd + h * HSd;
#pragma unroll
    for (int nt = 0; nt < 8; nt++) {
        int c0 = nt * 8 + 2 * t4;
        *(__half2*)(O + row0 + c0) = __floats2half2_rn(o[nt][0] * i0, o[nt][1] * i0);
        *(__half2*)(O + row1 + c0) = __floats2half2_rn(o[nt][2] * i1, o[nt][3] * i1);
    }
}

// ---------------- loss kernels ----------------
__global__ void zero_kernel(float* p, int n) {
    int i = blockIdx.x * blockDim.x + threadIdx.x;
    if (i < n) p[i] = 0.f;
}

__global__ __launch_bounds__(256) void lossfinal_kernel(const float* __restrict__ ls,
                                                        const float* __restrict__ logits,
                                                        const int* __restrict__ tgt,
                                                        float* __restrict__ out) {
    float s = 0.f;
    for (int r = threadIdx.x; r < NT; r += 256)
        s += logf(ls[r]) - logits[(size_t)r * Vv + tgt[r]];
    s = blockReduceSum256(s);
    if (threadIdx.x == 0) out[0] = s * (1.0f / NT);
}

__global__ __launch_bounds__(256) void lossreduce_kernel(const float* __restrict__ rl,
                                                         float* __restrict__ out) {
    float s = 0.f;
    for (int i = threadIdx.x; i < NT; i += 256) s += rl[i];
    s = blockReduceSum256(s);
    if (threadIdx.x == 0) out[0] = s * (1.0f / NT);
}

__global__ void lse_init_kernel(float* lm, float* ls, float* lt) {
    int i = blockIdx.x * blockDim.x + threadIdx.x;
    if (i < NT) { lm[i] = -1e30f; ls[i] = 0.f; lt[i] = 0.f; }
}

__global__ __launch_bounds__(256) void chunkloss_kernel(const float* __restrict__ chunk,
                                                        int width, int col0,
                                                        const int* __restrict__ tgt,
                                                        float* __restrict__ lm,
                                                        float* __restrict__ ls,
                                                        float* __restrict__ lt) {
    int r = blockIdx.x;
    const float* cr = chunk + (size_t)r * width;
    float m = -1e30f;
    for (int c = threadIdx.x; c < width; c += 256) m = fmaxf(m, cr[c]);
    m = blockReduceMax256(m);
    float s = 0.f;
    for (int c = threadIdx.x; c < width; c += 256) s += __expf(cr[c] - m);
    s = blockReduceSum256(s);
    if (threadIdx.x == 0) {
        float mOld = lm[r];
        float mNew = fmaxf(mOld, m);
        ls[r] = ls[r] * __expf(mOld - mNew) + s * __expf(m - mNew);
        lm[r] = mNew;
        int tg = tgt[r] - col0;
        if (tg >= 0 && tg < width) lt[r] = cr[tg];
    }
}

__global__ void chunkfinal_kernel(const float* lm, const float* ls, const float* lt,
                                  float* rl) {
    int i = blockIdx.x * blockDim.x + threadIdx.x;
    if (i < NT) rl[i] = lm[i] + logf(ls[i]) - lt[i];
}

// ---------------- host driver ----------------
static void* devptr(const void* sym) {
    void* p = nullptr;
    cudaGetSymbolAddress(&p, sym);
    return p;
}

extern "C" void kernel_launch(void* const* d_in, const int* in_sizes, int n_in,
                              void* d_out, int out_size) {
    const int* inputs    = (const int*)d_in[0];
    const int* targets   = (const int*)d_in[1];
    const float* tok     = (const float*)d_in[2];
    const float* pos     = (const float*)d_in[3];
    const float* ln1g    = (const float*)d_in[4];
    const float* ln1b    = (const float*)d_in[5];
    const float* ln2g    = (const float*)d_in[6];
    const float* ln2b    = (const float*)d_in[7];
    const float* wq      = (const float*)d_in[8];
    const float* wk      = (const float*)d_in[9];
    const float* wv      = (const float*)d_in[10];
    const float* wo      = (const float*)d_in[11];
    const float* bo      = (const float*)d_in[12];
    const float* w1      = (const float*)d_in[13];
    const float* b1      = (const float*)d_in[14];
    const float* w2      = (const float*)d_in[15];
    const float* b2      = (const float*)d_in[16];
    const float* lnfg    = (const float*)d_in[17];
    const float* lnfb    = (const float*)d_in[18];
    const float* whead   = (const float*)d_in[19];
    const float* bhead   = (const float*)d_in[20];

    float*  x   = (float*)devptr(g_x);
    __half* h   = (__half*)devptr(g_h);
    __half* qkv = (__half*)devptr(g_qkv);
    __half* ob  = (__half*)devptr(g_ob);
    __half* fb  = (__half*)devptr(g_f);
    float*  rl  = (float*)devptr(g_rowloss);
    float*  lm  = (float*)devptr(g_lm);
    float*  ls  = (float*)devptr(g_ls);
    float*  lt  = (float*)devptr(g_lt);
    __half* wth = (__half*)devptr(g_wth);

    cudaFuncSetAttribute(mma_gemm<false, false, false, false, true, false>, cudaFuncAttributeMaxDynamicSharedMemorySize, GEMM_SMEM);
    cudaFuncSetAttribute(mma_gemm<true, false, true, false, false, false>,  cudaFuncAttributeMaxDynamicSharedMemorySize, GEMM_SMEM);
    cudaFuncSetAttribute(mma_gemm<true, true, false, false, true, false>,   cudaFuncAttributeMaxDynamicSharedMemorySize, GEMM_SMEM);
    cudaFuncSetAttribute(mma_gemm<true, false, false, true, false, true>,   cudaFuncAttributeMaxDynamicSharedMemorySize, GEMM_SMEM);
    cudaFuncSetAttribute(mma_gemm<true, false, false, true, false, false>,  cudaFuncAttributeMaxDynamicSharedMemorySize, GEMM_SMEM);
    cudaFuncSetAttribute(attn_tc_kernel, cudaFuncAttributeMaxDynamicSharedMemorySize, ATTN_SMEM);

    // ---- weight prep: fp16 convert + transpose to [N][K], once per launch ----
    {
        dim3 blk(256);
        size_t cc = (size_t)Cd * Cd, cf = (size_t)Cd * Fd;
        dim3 gCC(Cd / 32, Cd / 64, Ll);
        transpose_h_kernel<<<gCC, blk>>>(wq, wth + OFF_QKV + (size_t)0 * cc, Cd, Cd, Cd, cc, (size_t)QKVS * Cd);
        transpose_h_kernel<<<gCC, blk>>>(wk, wth + OFF_QKV + (size_t)1 * cc, Cd, Cd, Cd, cc, (size_t)QKVS * Cd);
        transpose_h_kernel<<<gCC, blk>>>(wv, wth + OFF_QKV + (size_t)2 * cc, Cd, Cd, Cd, cc, (size_t)QKVS * Cd);
        transpose_h_kernel<<<gCC, blk>>>(wo, wth + OFF_WO, Cd, Cd, Cd, cc, cc);
        dim3 gW1(Fd / 32, Cd / 64, Ll);
        transpose_h_kernel<<<gW1, blk>>>(w1, wth + OFF_W1, Cd, Fd, Fd, cf, cf);
        dim3 gW2(Cd / 32, Fd / 64, Ll);
        transpose_h_kernel<<<gW2, blk>>>(w2, wth + OFF_W2, Fd, Cd, Cd, cf, cf);
        dim3 gHd(VPAD / 32, Cd / 64, 1);
        transpose_h_kernel<<<gHd, blk>>>(whead, wth + OFF_HD, Cd, Vv, VPAD, 0, 0);
    }

    dim3 gAttn(Tt / 64, Bq * Hh);

    embed_kernel<<<NT, 192>>>(inputs, tok, pos, x);

    for (int l = 0; l < Ll; l++) {
        const __half* wqkv = wth + OFF_QKV + (size_t)l * Cd * QKVS;
        const __half* wot  = wth + OFF_WO + (size_t)l * Cd * Cd;
        const __half* w1t  = wth + OFF_W1 + (size_t)l * Cd * Fd;
        const __half* w2t  = wth + OFF_W2 + (size_t)l * Fd * Cd;

        ln_kernel<<<NT / 8, 256>>>(x, ln1g + l * Cd, ln1b + l * Cd, h);
        mma_gemm<false, false, false, false, true, false><<<GEMM_GRID, 256, GEMM_SMEM>>>(
            h, wqkv, nullptr, nullptr, qkv, NT, QKVS, Cd, QKVS / 128, nullptr);
        attn_tc_kernel<<<gAttn, 128, ATTN_SMEM>>>(qkv, ob);
        mma_gemm<true, false, true, false, false, false><<<GEMM_GRID, 256, GEMM_SMEM>>>(
            ob, wot, bo + l * Cd, x, x, NT, Cd, Cd, Cd / 128, nullptr);
        ln_kernel<<<NT / 8, 256>>>(x, ln2g + l * Cd, ln2b + l * Cd, h);
        mma_gemm<true, true, false, false, true, false><<<GEMM_GRID, 256, GEMM_SMEM>>>(
            h, w1t, b1 + (size_t)l * Fd, nullptr, fb, NT, Fd, Cd, Fd / 128, nullptr);
        mma_gemm<true, false, true, false, false, false><<<GEMM_GRID, 256, GEMM_SMEM>>>(
            fb, w2t, b2 + l * Cd, x, x, NT, Cd, Fd, Cd / 128, nullptr);
    }

    ln_kernel<<<NT / 8, 256>>>(x, lnfg, lnfb, h);

    const long long NV = (long long)NT * Vv;
    if ((long long)out_size >= NV) {
        float* logits = (float*)d_out;
        bool wantLoss = ((long long)out_size > NV);
        if (wantLoss) {
            zero_kernel<<<(NT + 255) / 256, 256>>>(ls, NT);
            mma_gemm<true, false, false, true, false, true><<<GEMM_GRID, 256, GEMM_SMEM>>>(
                h, wth + OFF_HD, bhead, nullptr, logits, NT, Vv, Cd, VPAD / 128, ls);
            lossfinal_kernel<<<1, 256>>>(ls, logits, targets, (float*)d_out + NV);
        } else {
            mma_gemm<true, false, false, true, false, false><<<GEMM_GRID, 256, GEMM_SMEM>>>(
                h, wth + OFF_HD, bhead, nullptr, logits, NT, Vv, Cd, VPAD / 128, nullptr);
        }
    } else {
        h2f_kernel<<<2048, 256>>>(h, x, (size_t)NT * Cd);
        lse_init_kernel<<<(NT + 255) / 256, 256>>>(lm, ls, lt);
        const int CW = 3072;
        float* fbuf = (float*)devptr(g_f);
        for (int col0 = 0; col0 < Vv; col0 += CW) {
            int width = (Vv - col0 < CW) ? (Vv - col0) : CW;
            dim3 gCk(NT / 128, (width + 63) / 64);
            sgemm_kernel<true, false, false><<<gCk, 256>>>(x, whead + col0, bhead + col0,
                                                           nullptr, fbuf, NT, width, Cd, Vv);
            chunkloss_kernel<<<NT, 256>>>(fbuf, width, col0, targets, lm, ls, lt);
        }
        chunkfinal_kernel<<<(NT + 255) / 256, 256>>>(lm, ls, lt, rl);
        lossreduce_kernel<<<1, 256>>>(rl, (float*)d_out);
    }
}